// round 12
// baseline (speedup 1.0000x reference)
#include <cuda_runtime.h>
#include <cstdint>
#include <mma.h>
#include <math.h>

using namespace nvcuda;

#define NV 100000
#define NE 3200000
#define NBLK 391          // ceil(NV/256)

// ---------------- scratch (device globals: allocation-free) ----------------
__device__ int   g_is64;
__device__ float g_dinv[NV];
__device__ int   g_indeg[NV];
__device__ int   g_rowptr[NV + 1];
__device__ int   g_cursor[NV];
__device__ int   g_bsum[NBLK];
__device__ int   g_boff[NBLK];
__device__ int   g_col[NE];
__device__ float g_a [NV * 128];   // aggregated features (128-dim)
__device__ float g_h [NV * 128];   // hidden (128-dim)
__device__ float g_x1[NV * 512];   // 512-dim buffer A
__device__ float g_x2[NV * 512];   // 512-dim buffer B

// ---------------- init + dtype detection (fused) ---------------------------
__global__ void k_init_detect(const int* ei32) {
    int i = blockIdx.x * blockDim.x + threadIdx.x;
    if (i < NV) g_indeg[i] = 0;
    if (blockIdx.x == 0) {
        __shared__ int nz;
        if (threadIdx.x == 0) nz = 0;
        __syncthreads();
        int c = 0;
        for (int k = threadIdx.x; k < 2048; k += blockDim.x)
            if (ei32[2 * k + 1] != 0) c = 1;
        if (c) atomicExch(&nz, 1);
        __syncthreads();
        if (threadIdx.x == 0) g_is64 = (nz == 0) ? 1 : 0;
    }
}

// ---------------- degree histogram (2 edges / thread) ----------------------
__global__ void k_hist(const void* ei) {
    int e = blockIdx.x * blockDim.x + threadIdx.x;   // pair index
    if (e * 2 >= NE) return;
    int d0, d1;
    if (g_is64) {
        longlong2 v = ((const longlong2*)ei)[NE / 2 + e];
        d0 = (int)v.x; d1 = (int)v.y;
    } else {
        int2 v = ((const int2*)ei)[NE / 2 + e];
        d0 = v.x; d1 = v.y;
    }
    atomicAdd(&g_indeg[d0], 1);
    atomicAdd(&g_indeg[d1], 1);
}

// ---------------- 3-phase scan (reduce / scan block sums / scatter) --------
__global__ void __launch_bounds__(256) k_reduce() {
    int i = blockIdx.x * 256 + threadIdx.x;
    int v = (i < NV) ? g_indeg[i] : 0;
#pragma unroll
    for (int o = 16; o; o >>= 1) v += __shfl_xor_sync(0xFFFFFFFFu, v, o);
    __shared__ int ws[8];
    if ((threadIdx.x & 31) == 0) ws[threadIdx.x >> 5] = v;
    __syncthreads();
    if (threadIdx.x == 0) {
        int s = 0;
#pragma unroll
        for (int j = 0; j < 8; j++) s += ws[j];
        g_bsum[blockIdx.x] = s;
    }
}

__global__ void __launch_bounds__(512) k_scanb() {
    int t = threadIdx.x;
    int v = (t < NBLK) ? g_bsum[t] : 0;
    int incl = v;
#pragma unroll
    for (int o = 1; o < 32; o <<= 1) {
        int n = __shfl_up_sync(0xFFFFFFFFu, incl, o);
        if ((t & 31) >= o) incl += n;
    }
    __shared__ int ws[16];
    if ((t & 31) == 31) ws[t >> 5] = incl;
    __syncthreads();
    if (t == 0) {
        int run = 0;
#pragma unroll
        for (int j = 0; j < 16; j++) { int x = ws[j]; ws[j] = run; run += x; }
    }
    __syncthreads();
    if (t < NBLK) g_boff[t] = incl - v + ws[t >> 5];
}

__global__ void __launch_bounds__(256) k_scatter() {
    int b = blockIdx.x, t = threadIdx.x;
    int i = b * 256 + t;
    int v = (i < NV) ? g_indeg[i] : 0;
    int incl = v;
#pragma unroll
    for (int o = 1; o < 32; o <<= 1) {
        int n = __shfl_up_sync(0xFFFFFFFFu, incl, o);
        if ((t & 31) >= o) incl += n;
    }
    __shared__ int ws[8];
    if ((t & 31) == 31) ws[t >> 5] = incl;
    __syncthreads();
    if (t == 0) {
        int run = 0;
#pragma unroll
        for (int j = 0; j < 8; j++) { int x = ws[j]; ws[j] = run; run += x; }
    }
    __syncthreads();
    int ex = incl - v + ws[t >> 5] + g_boff[b];
    if (i < NV) {
        g_rowptr[i] = ex;
        g_cursor[i] = ex;
        g_dinv[i]   = rsqrtf((float)(v + 1));   // +1 self-loop
        if (i == NV - 1) g_rowptr[NV] = ex + v;
    }
}

// ---------------- CSR fill (2 edges / thread) ------------------------------
__global__ void k_fill(const void* ei) {
    int e = blockIdx.x * blockDim.x + threadIdx.x;   // pair index
    if (e * 2 >= NE) return;
    int s0, s1, d0, d1;
    if (g_is64) {
        longlong2 sv = ((const longlong2*)ei)[e];
        longlong2 dv = ((const longlong2*)ei)[NE / 2 + e];
        s0 = (int)sv.x; s1 = (int)sv.y;
        d0 = (int)dv.x; d1 = (int)dv.y;
    } else {
        int2 sv = ((const int2*)ei)[e];
        int2 dv = ((const int2*)ei)[NE / 2 + e];
        s0 = sv.x; s1 = sv.y;
        d0 = dv.x; d1 = dv.y;
    }
    int p0 = atomicAdd(&g_cursor[d0], 1);
    g_col[p0] = s0;
    int p1 = atomicAdd(&g_cursor[d1], 1);
    g_col[p1] = s1;
}

// ---------------- aggregation: warp per node, float4 per lane --------------
__global__ void __launch_bounds__(256) k_agg(const float4* __restrict__ xin,
                                             float4* __restrict__ xout) {
    int w = (blockIdx.x << 3) + (threadIdx.x >> 5);   // node
    if (w >= NV) return;
    int lane = threadIdx.x & 31;
    float dv = g_dinv[w];
    float4 xv = xin[(size_t)w * 32 + lane];
    float4 acc;
    float dvv = dv * dv;
    acc.x = dvv * xv.x; acc.y = dvv * xv.y; acc.z = dvv * xv.z; acc.w = dvv * xv.w;
    int e  = g_rowptr[w];
    int e1 = g_rowptr[w + 1];
    for (; e + 3 < e1; e += 4) {
        int s0 = g_col[e],     s1 = g_col[e + 1];
        int s2 = g_col[e + 2], s3 = g_col[e + 3];
        float w0 = dv * g_dinv[s0], w1 = dv * g_dinv[s1];
        float w2 = dv * g_dinv[s2], w3 = dv * g_dinv[s3];
        float4 v0 = xin[(size_t)s0 * 32 + lane];
        float4 v1 = xin[(size_t)s1 * 32 + lane];
        float4 v2 = xin[(size_t)s2 * 32 + lane];
        float4 v3 = xin[(size_t)s3 * 32 + lane];
        acc.x += w0 * v0.x + w1 * v1.x + w2 * v2.x + w3 * v3.x;
        acc.y += w0 * v0.y + w1 * v1.y + w2 * v2.y + w3 * v3.y;
        acc.z += w0 * v0.z + w1 * v1.z + w2 * v2.z + w3 * v3.z;
        acc.w += w0 * v0.w + w1 * v1.w + w2 * v2.w + w3 * v3.w;
    }
    for (; e < e1; e++) {
        int s = g_col[e];
        float ws = dv * g_dinv[s];
        float4 v = xin[(size_t)s * 32 + lane];
        acc.x += ws * v.x; acc.y += ws * v.y; acc.z += ws * v.z; acc.w += ws * v.w;
    }
    xout[(size_t)w * 32 + lane] = acc;
}

// ---------------- cp.async helpers ----------------
__device__ __forceinline__ void cp16(void* dst, const void* src, bool pred) {
    unsigned int d = (unsigned int)__cvta_generic_to_shared(dst);
    int sz = pred ? 16 : 0;
    asm volatile("cp.async.cg.shared.global [%0], [%1], 16, %2;"
                 :: "r"(d), "l"(src), "r"(sz));
}
__device__ __forceinline__ void cp_commit() {
    asm volatile("cp.async.commit_group;");
}
template <int N>
__device__ __forceinline__ void cp_wait() {
    asm volatile("cp.async.wait_group %0;" :: "n"(N));
}

// ---------------- TF32 tensor GEMM, cp.async double-buffered, BK=32 --------
// Block tile 128x128, 2 stages, dynamic smem (70656 B). 8 warps (4Mx2N),
// warp tile 32x64.
constexpr int GM_BM = 128, GM_BN = 128, GM_BK = 32;
constexpr int GM_LDA = GM_BK + 4;    // 36
constexpr int GM_LDB = GM_BN + 4;    // 132
constexpr int GM_ASZ = GM_BM * GM_LDA;   // 4608 floats
constexpr int GM_BSZ = GM_BK * GM_LDB;   // 4224 floats
constexpr int GM_SMEM_BYTES = 2 * (GM_ASZ + GM_BSZ) * 4;   // 70656

template <bool RELU>
__global__ void __launch_bounds__(256, 2) k_tgemm(const float* __restrict__ A,
                                                  const float* __restrict__ B,
                                                  const float* __restrict__ bias,
                                                  float* __restrict__ C,
                                                  int M, int K, int N) {
    extern __shared__ float smem[];
    float* As = smem;                    // 2 stages
    float* Bs = smem + 2 * GM_ASZ;       // 2 stages

    int tid  = threadIdx.x;
    int warp = tid >> 5;
    int lane = tid & 31;
    int m0 = blockIdx.y * GM_BM, n0 = blockIdx.x * GM_BN;
    int wm = warp & 3, wn = warp >> 2;

    wmma::fragment<wmma::accumulator, 16, 16, 8, float> acc[2][4];
#pragma unroll
    for (int i = 0; i < 2; i++)
#pragma unroll
        for (int j = 0; j < 4; j++) wmma::fill_fragment(acc[i][j], 0.0f);

    int KT = K / GM_BK;

    auto load_tile = [&](int t, int buf) {
        int k0 = t * GM_BK;
        float* Ab = As + buf * GM_ASZ;
        float* Bb = Bs + buf * GM_BSZ;
        // A tile 128x32 = 1024 float4, 4 per thread
#pragma unroll
        for (int i = 0; i < 4; i++) {
            int idx = tid + 256 * i;
            int r = idx >> 3, c = (idx & 7) * 4;
            bool ok = (m0 + r) < M;
            cp16(&Ab[r * GM_LDA + c], &A[(size_t)(m0 + r) * K + k0 + c], ok);
        }
        // B tile 32x128 = 1024 float4, 4 per thread
#pragma unroll
        for (int i = 0; i < 4; i++) {
            int idx = tid + 256 * i;
            int r = idx >> 5, c = (idx & 31) * 4;
            cp16(&Bb[r * GM_LDB + c], &B[(size_t)(k0 + r) * N + n0 + c], true);
        }
        cp_commit();
    };

    load_tile(0, 0);
    for (int t = 0; t < KT; t++) {
        int cur = t & 1;
        if (t + 1 < KT) {
            load_tile(t + 1, cur ^ 1);
            cp_wait<1>();
        } else {
            cp_wait<0>();
        }
        __syncthreads();
        float* Ab = As + cur * GM_ASZ;
        float* Bb = Bs + cur * GM_BSZ;
#pragma unroll
        for (int kk = 0; kk < GM_BK; kk += 8) {
            wmma::fragment<wmma::matrix_a, 16, 16, 8, wmma::precision::tf32,
                           wmma::row_major> af[2];
            wmma::fragment<wmma::matrix_b, 16, 16, 8, wmma::precision::tf32,
                           wmma::row_major> bf[4];
#pragma unroll
            for (int i = 0; i < 2; i++)
                wmma::load_matrix_sync(af[i], &Ab[(wm * 32 + i * 16) * GM_LDA + kk],
                                       GM_LDA);
#pragma unroll
            for (int j = 0; j < 4; j++)
                wmma::load_matrix_sync(bf[j], &Bb[kk * GM_LDB + wn * 64 + j * 16],
                                       GM_LDB);
#pragma unroll
            for (int i = 0; i < 2; i++)
#pragma unroll
                for (int j = 0; j < 4; j++)
                    wmma::mma_sync(acc[i][j], af[i], bf[j], acc[i][j]);
        }
        __syncthreads();
    }

    // epilogue: per-warp 16x16 staging (ld=20) in smem, bias+relu, float4 out
    float* stage = smem + warp * 320;
#pragma unroll
    for (int i = 0; i < 2; i++) {
#pragma unroll
        for (int j = 0; j < 4; j++) {
            wmma::store_matrix_sync(stage, acc[i][j], 20, wmma::mem_row_major);
            __syncwarp();
            int r  = lane >> 1;
            int cs = (lane & 1) * 8;
            int gm = m0 + wm * 32 + i * 16 + r;
            int gn = n0 + wn * 64 + j * 16 + cs;
            if (gm < M) {
                const float* sp = &stage[r * 20 + cs];
                float4 o0, o1;
                o0.x = sp[0] + bias[gn + 0]; o0.y = sp[1] + bias[gn + 1];
                o0.z = sp[2] + bias[gn + 2]; o0.w = sp[3] + bias[gn + 3];
                o1.x = sp[4] + bias[gn + 4]; o1.y = sp[5] + bias[gn + 5];
                o1.z = sp[6] + bias[gn + 6]; o1.w = sp[7] + bias[gn + 7];
                if (RELU) {
                    o0.x = fmaxf(o0.x, 0.f); o0.y = fmaxf(o0.y, 0.f);
                    o0.z = fmaxf(o0.z, 0.f); o0.w = fmaxf(o0.w, 0.f);
                    o1.x = fmaxf(o1.x, 0.f); o1.y = fmaxf(o1.y, 0.f);
                    o1.z = fmaxf(o1.z, 0.f); o1.w = fmaxf(o1.w, 0.f);
                }
                *(float4*)&C[(size_t)gm * N + gn]     = o0;
                *(float4*)&C[(size_t)gm * N + gn + 4] = o1;
            }
            __syncwarp();
        }
    }
}

// ---------------- final projection 512 -> 3 ----------------
__global__ void __launch_bounds__(256) k_out3(const float* __restrict__ h,
                                              const float* __restrict__ Wc,
                                              const float* __restrict__ bc,
                                              float* __restrict__ out) {
    __shared__ float wc[512 * 3];
    for (int i = threadIdx.x; i < 512 * 3; i += blockDim.x) wc[i] = Wc[i];
    __syncthreads();
    int gw   = (blockIdx.x * blockDim.x + threadIdx.x) >> 5;
    int lane = threadIdx.x & 31;
    if (gw >= NV) return;
    float a0 = 0.f, a1 = 0.f, a2 = 0.f;
#pragma unroll
    for (int i = 0; i < 16; i++) {
        int k = lane + 32 * i;
        float hv = h[gw * 512 + k];
        a0 += hv * wc[k * 3 + 0];
        a1 += hv * wc[k * 3 + 1];
        a2 += hv * wc[k * 3 + 2];
    }
#pragma unroll
    for (int o = 16; o; o >>= 1) {
        a0 += __shfl_xor_sync(0xFFFFFFFFu, a0, o);
        a1 += __shfl_xor_sync(0xFFFFFFFFu, a1, o);
        a2 += __shfl_xor_sync(0xFFFFFFFFu, a2, o);
    }
    if (lane == 0) {
        out[gw * 3 + 0] = a0 + bc[0];
        out[gw * 3 + 1] = a1 + bc[1];
        out[gw * 3 + 2] = a2 + bc[2];
    }
}

// ---------------- launch ----------------
extern "C" void kernel_launch(void* const* d_in, const int* in_sizes, int n_in,
                              void* d_out, int out_size) {
    const float* x  = (const float*)d_in[0];
    const void*  ei = d_in[1];
    const float* W1 = (const float*)d_in[2];
    const float* b1 = (const float*)d_in[3];
    const float* W2 = (const float*)d_in[4];
    const float* b2 = (const float*)d_in[5];
    const float* W3 = (const float*)d_in[6];
    const float* b3 = (const float*)d_in[7];
    const float* Wi = (const float*)d_in[8];
    const float* bi = (const float*)d_in[9];
    const float* Wc = (const float*)d_in[10];
    const float* bc = (const float*)d_in[11];
    float* out = (float*)d_out;

    float *pA, *pH, *pX1, *pX2;
    cudaGetSymbolAddress((void**)&pA,  g_a);
    cudaGetSymbolAddress((void**)&pH,  g_h);
    cudaGetSymbolAddress((void**)&pX1, g_x1);
    cudaGetSymbolAddress((void**)&pX2, g_x2);

    cudaFuncSetAttribute(k_tgemm<true>,
                         cudaFuncAttributeMaxDynamicSharedMemorySize,
                         GM_SMEM_BYTES);

    const int TB  = 256;
    const int NPB = (NE / 2 + TB - 1) / TB;   // edge-pair blocks
    const int MT  = (NV + 127) / 128;
    const int AGB = (NV + 7) / 8;

    // preprocessing
    k_init_detect<<<NBLK, TB>>>((const int*)ei);
    k_hist<<<NPB, TB>>>(ei);
    k_reduce<<<NBLK, TB>>>();
    k_scanb<<<1, 512>>>();
    k_scatter<<<NBLK, TB>>>();
    k_fill<<<NPB, TB>>>(ei);

    // layer 1
    k_agg<<<AGB, TB>>>((const float4*)x, (float4*)pA);
    k_tgemm<true><<<dim3(1, MT), 256, GM_SMEM_BYTES>>>(pA, W1, b1, pH, NV, 128, 128);
    // layer 2
    k_agg<<<AGB, TB>>>((const float4*)pH, (float4*)pA);
    k_tgemm<true><<<dim3(1, MT), 256, GM_SMEM_BYTES>>>(pA, W2, b2, pH, NV, 128, 128);
    // layer 3: agg 128-dim, project 128->512
    k_agg<<<AGB, TB>>>((const float4*)pH, (float4*)pA);
    k_tgemm<true><<<dim3(4, MT), 256, GM_SMEM_BYTES>>>(pA, W3, b3, pX1, NV, 128, 512);
    // MLP 512->512
    k_tgemm<true><<<dim3(4, MT), 256, GM_SMEM_BYTES>>>(pX1, Wi, bi, pX2, NV, 512, 512);
    // classifier
    k_out3<<<(NV * 32 + TB - 1) / TB, TB>>>(pX2, Wc, bc, out);
}

// round 14
// speedup vs baseline: 2.1869x; 2.1869x over previous
#include <cuda_runtime.h>
#include <cuda_fp16.h>
#include <cstdint>
#include <mma.h>
#include <math.h>

using namespace nvcuda;

#define NV 100000
#define NE 3200000
#define NBLK 391          // ceil(NV/256)
#define MT128 782         // ceil(NV/128)

// ---------------- scratch (device globals: allocation-free) ----------------
__device__ int    g_is64;
__device__ float  g_dinv[NV];
__device__ int    g_indeg[NV];
__device__ int    g_rowptr[NV + 1];
__device__ int    g_cursor[NV];
__device__ int    g_bsum[NBLK];
__device__ int    g_boff[NBLK];
__device__ int    g_col[NE];
__device__ __half g_xh[NV * 128];      // half(x)
__device__ __half g_ah[NV * 128];      // gemm out / agg in
__device__ __half g_hh[NV * 128];      // agg out / gemm in
__device__ __half g_y1[NV * 512];
__device__ __half g_y2[NV * 512];
__device__ __half g_w1h[128 * 128];
__device__ __half g_w2h[128 * 128];
__device__ __half g_w3h[128 * 512];
__device__ __half g_wih[512 * 512];

// ---------------- half<->float helpers ----------------
__device__ __forceinline__ float4 h4tof4(uint2 v) {
    __half2 h0 = *(__half2*)&v.x;
    __half2 h1 = *(__half2*)&v.y;
    float2 f0 = __half22float2(h0), f1 = __half22float2(h1);
    return make_float4(f0.x, f0.y, f1.x, f1.y);
}
__device__ __forceinline__ uint2 f4toh4(float4 f) {
    __half2 h0 = __floats2half2_rn(f.x, f.y);
    __half2 h1 = __floats2half2_rn(f.z, f.w);
    uint2 o;
    o.x = *(unsigned*)&h0;
    o.y = *(unsigned*)&h1;
    return o;
}

// float -> half conversion, 4 elems/thread
__global__ void k_f2h(const float4* __restrict__ src, uint2* __restrict__ dst,
                      int n4) {
    int i = blockIdx.x * blockDim.x + threadIdx.x;
    if (i >= n4) return;
    dst[i] = f4toh4(src[i]);
}

// ---------------- cp.async helpers ----------------
__device__ __forceinline__ uint32_t smem_u32(const void* p) {
    return (uint32_t)__cvta_generic_to_shared(p);
}
__device__ __forceinline__ void cp16_sh(uint32_t dst, const void* src, bool pred) {
    int sz = pred ? 16 : 0;
    asm volatile("cp.async.cg.shared.global [%0], [%1], 16, %2;"
                 :: "r"(dst), "l"(src), "r"(sz));
}
__device__ __forceinline__ void cp_commit() {
    asm volatile("cp.async.commit_group;");
}
template <int N>
__device__ __forceinline__ void cp_wait() {
    asm volatile("cp.async.wait_group %0;" :: "n"(N));
}

// ---------------- init + dtype detection (fused) ---------------------------
__global__ void k_init_detect(const int* ei32) {
    int i = blockIdx.x * blockDim.x + threadIdx.x;
    if (i < NV) g_indeg[i] = 0;
    if (blockIdx.x == 0) {
        __shared__ int nz;
        if (threadIdx.x == 0) nz = 0;
        __syncthreads();
        int c = 0;
        for (int k = threadIdx.x; k < 2048; k += blockDim.x)
            if (ei32[2 * k + 1] != 0) c = 1;
        if (c) atomicExch(&nz, 1);
        __syncthreads();
        if (threadIdx.x == 0) g_is64 = (nz == 0) ? 1 : 0;
    }
}

// ---------------- degree histogram (2 edges / thread) ----------------------
__global__ void k_hist(const void* ei) {
    int e = blockIdx.x * blockDim.x + threadIdx.x;
    if (e * 2 >= NE) return;
    int d0, d1;
    if (g_is64) {
        longlong2 v = ((const longlong2*)ei)[NE / 2 + e];
        d0 = (int)v.x; d1 = (int)v.y;
    } else {
        int2 v = ((const int2*)ei)[NE / 2 + e];
        d0 = v.x; d1 = v.y;
    }
    atomicAdd(&g_indeg[d0], 1);
    atomicAdd(&g_indeg[d1], 1);
}

// ---------------- 3-phase scan ----------------
__global__ void __launch_bounds__(256) k_reduce() {
    int i = blockIdx.x * 256 + threadIdx.x;
    int v = (i < NV) ? g_indeg[i] : 0;
#pragma unroll
    for (int o = 16; o; o >>= 1) v += __shfl_xor_sync(0xFFFFFFFFu, v, o);
    __shared__ int ws[8];
    if ((threadIdx.x & 31) == 0) ws[threadIdx.x >> 5] = v;
    __syncthreads();
    if (threadIdx.x == 0) {
        int s = 0;
#pragma unroll
        for (int j = 0; j < 8; j++) s += ws[j];
        g_bsum[blockIdx.x] = s;
    }
}

__global__ void __launch_bounds__(512) k_scanb() {
    int t = threadIdx.x;
    int v = (t < NBLK) ? g_bsum[t] : 0;
    int incl = v;
#pragma unroll
    for (int o = 1; o < 32; o <<= 1) {
        int n = __shfl_up_sync(0xFFFFFFFFu, incl, o);
        if ((t & 31) >= o) incl += n;
    }
    __shared__ int ws[16];
    if ((t & 31) == 31) ws[t >> 5] = incl;
    __syncthreads();
    if (t == 0) {
        int run = 0;
#pragma unroll
        for (int j = 0; j < 16; j++) { int x = ws[j]; ws[j] = run; run += x; }
    }
    __syncthreads();
    if (t < NBLK) g_boff[t] = incl - v + ws[t >> 5];
}

__global__ void __launch_bounds__(256) k_scatter() {
    int b = blockIdx.x, t = threadIdx.x;
    int i = b * 256 + t;
    int v = (i < NV) ? g_indeg[i] : 0;
    int incl = v;
#pragma unroll
    for (int o = 1; o < 32; o <<= 1) {
        int n = __shfl_up_sync(0xFFFFFFFFu, incl, o);
        if ((t & 31) >= o) incl += n;
    }
    __shared__ int ws[8];
    if ((t & 31) == 31) ws[t >> 5] = incl;
    __syncthreads();
    if (t == 0) {
        int run = 0;
#pragma unroll
        for (int j = 0; j < 8; j++) { int x = ws[j]; ws[j] = run; run += x; }
    }
    __syncthreads();
    int ex = incl - v + ws[t >> 5] + g_boff[b];
    if (i < NV) {
        g_rowptr[i] = ex;
        g_cursor[i] = ex;
        g_dinv[i]   = rsqrtf((float)(v + 1));
        if (i == NV - 1) g_rowptr[NV] = ex + v;
    }
}

__global__ void k_fill(const void* ei) {
    int e = blockIdx.x * blockDim.x + threadIdx.x;
    if (e * 2 >= NE) return;
    int s0, s1, d0, d1;
    if (g_is64) {
        longlong2 sv = ((const longlong2*)ei)[e];
        longlong2 dv = ((const longlong2*)ei)[NE / 2 + e];
        s0 = (int)sv.x; s1 = (int)sv.y;
        d0 = (int)dv.x; d1 = (int)dv.y;
    } else {
        int2 sv = ((const int2*)ei)[e];
        int2 dv = ((const int2*)ei)[NE / 2 + e];
        s0 = sv.x; s1 = sv.y;
        d0 = dv.x; d1 = dv.y;
    }
    int p0 = atomicAdd(&g_cursor[d0], 1);
    g_col[p0] = s0;
    int p1 = atomicAdd(&g_cursor[d1], 1);
    g_col[p1] = s1;
}

// ---------------- aggregation: warp/node, half4/lane, fp32 accumulate ------
template <bool BR>
__global__ void __launch_bounds__(256) k_aggh(const uint2* __restrict__ xin,
                                              uint2* __restrict__ xout,
                                              const float4* __restrict__ bias4) {
    int w = (blockIdx.x << 3) + (threadIdx.x >> 5);
    if (w >= NV) return;
    int lane = threadIdx.x & 31;
    float dv = g_dinv[w];
    float4 xv = h4tof4(xin[(size_t)w * 32 + lane]);
    float dvv = dv * dv;
    float4 acc;
    acc.x = dvv * xv.x; acc.y = dvv * xv.y; acc.z = dvv * xv.z; acc.w = dvv * xv.w;
    int e  = g_rowptr[w];
    int e1 = g_rowptr[w + 1];
    for (; e + 3 < e1; e += 4) {
        int s0 = g_col[e],     s1 = g_col[e + 1];
        int s2 = g_col[e + 2], s3 = g_col[e + 3];
        float w0 = dv * g_dinv[s0], w1 = dv * g_dinv[s1];
        float w2 = dv * g_dinv[s2], w3 = dv * g_dinv[s3];
        float4 v0 = h4tof4(xin[(size_t)s0 * 32 + lane]);
        float4 v1 = h4tof4(xin[(size_t)s1 * 32 + lane]);
        float4 v2 = h4tof4(xin[(size_t)s2 * 32 + lane]);
        float4 v3 = h4tof4(xin[(size_t)s3 * 32 + lane]);
        acc.x += w0 * v0.x + w1 * v1.x + w2 * v2.x + w3 * v3.x;
        acc.y += w0 * v0.y + w1 * v1.y + w2 * v2.y + w3 * v3.y;
        acc.z += w0 * v0.z + w1 * v1.z + w2 * v2.z + w3 * v3.z;
        acc.w += w0 * v0.w + w1 * v1.w + w2 * v2.w + w3 * v3.w;
    }
    for (; e < e1; e++) {
        int s = g_col[e];
        float ws = dv * g_dinv[s];
        float4 v = h4tof4(xin[(size_t)s * 32 + lane]);
        acc.x += ws * v.x; acc.y += ws * v.y; acc.z += ws * v.z; acc.w += ws * v.w;
    }
    if (BR) {
        float4 b = bias4[lane];
        acc.x = fmaxf(acc.x + b.x, 0.f);
        acc.y = fmaxf(acc.y + b.y, 0.f);
        acc.z = fmaxf(acc.z + b.z, 0.f);
        acc.w = fmaxf(acc.w + b.w, 0.f);
    }
    xout[(size_t)w * 32 + lane] = f4toh4(acc);
}

// ---------------- fp16 tensor GEMM: C = A[M,K] @ B[K,N] (+bias,relu) -------
// 128x128 tile, BK=32, 2-stage cp.async, fp32 accumulate, half in/out.
constexpr int HBK  = 32;
constexpr int HLDA = HBK + 8;     // 40 halves (80 B rows)
constexpr int HLDB = 128 + 8;     // 136 halves (272 B rows)
constexpr int HASZ = 128 * HLDA;  // 5120 halves / stage
constexpr int HBSZ = HBK * HLDB;  // 4352 halves / stage

template <bool BR>
__global__ void __launch_bounds__(256, 2) k_hgemm(const __half* __restrict__ A,
                                                  const __half* __restrict__ B,
                                                  const float* __restrict__ bias,
                                                  __half* __restrict__ C,
                                                  int M, int K, int N) {
    __shared__ __half sA[2 * HASZ];
    __shared__ __half sB[2 * HBSZ];

    int tid  = threadIdx.x;
    int warp = tid >> 5;
    int lane = tid & 31;
    int m0 = blockIdx.y << 7, n0 = blockIdx.x << 7;
    int wm = warp & 3, wn = warp >> 2;   // 4 M x 2 N, warp tile 32x64

    wmma::fragment<wmma::accumulator, 16, 16, 16, float> acc[2][4];
#pragma unroll
    for (int i = 0; i < 2; i++)
#pragma unroll
        for (int j = 0; j < 4; j++) wmma::fill_fragment(acc[i][j], 0.0f);

    int KT = K / HBK;

    auto load_tile = [&](int t, int buf) {
        int k0 = t * HBK;
        // A tile 128x32 halves = 512 x 16B chunks, 2/thread
#pragma unroll
        for (int i = 0; i < 2; i++) {
            int idx = tid + 256 * i;
            int r = idx >> 2, c = (idx & 3) * 8;
            bool ok = (m0 + r) < M;
            cp16_sh(smem_u32(&sA[buf * HASZ + r * HLDA + c]),
                    A + (size_t)(m0 + r) * K + k0 + c, ok);
        }
        // B tile 32x128 halves = 512 x 16B chunks, 2/thread
#pragma unroll
        for (int i = 0; i < 2; i++) {
            int idx = tid + 256 * i;
            int r = idx >> 4, c = (idx & 15) * 8;
            cp16_sh(smem_u32(&sB[buf * HBSZ + r * HLDB + c]),
                    B + (size_t)(k0 + r) * N + n0 + c, true);
        }
        cp_commit();
    };

    load_tile(0, 0);
    for (int t = 0; t < KT; t++) {
        int cur = t & 1;
        if (t + 1 < KT) {
            load_tile(t + 1, cur ^ 1);
            cp_wait<1>();
        } else {
            cp_wait<0>();
        }
        __syncthreads();
        __half* Ab = sA + cur * HASZ;
        __half* Bb = sB + cur * HBSZ;
#pragma unroll
        for (int kk = 0; kk < HBK; kk += 16) {
            wmma::fragment<wmma::matrix_a, 16, 16, 16, __half, wmma::row_major> af[2];
            wmma::fragment<wmma::matrix_b, 16, 16, 16, __half, wmma::row_major> bf[4];
#pragma unroll
            for (int i = 0; i < 2; i++)
                wmma::load_matrix_sync(af[i], &Ab[(wm * 32 + i * 16) * HLDA + kk],
                                       HLDA);
#pragma unroll
            for (int j = 0; j < 4; j++)
                wmma::load_matrix_sync(bf[j], &Bb[kk * HLDB + wn * 64 + j * 16],
                                       HLDB);
#pragma unroll
            for (int i = 0; i < 2; i++)
#pragma unroll
                for (int j = 0; j < 4; j++)
                    wmma::mma_sync(acc[i][j], af[i], bf[j], acc[i][j]);
        }
        __syncthreads();
    }

    // epilogue: per-warp fp32 stage (16x20) in reused sA, bias+relu, half out
    float* stage = reinterpret_cast<float*>(sA) + warp * 320;
#pragma unroll
    for (int i = 0; i < 2; i++) {
#pragma unroll
        for (int j = 0; j < 4; j++) {
            wmma::store_matrix_sync(stage, acc[i][j], 20, wmma::mem_row_major);
            __syncwarp();
            int r  = lane >> 1;
            int cs = (lane & 1) * 8;
            int gm = m0 + wm * 32 + i * 16 + r;
            int gn = n0 + wn * 64 + j * 16 + cs;
            if (gm < M) {
                const float* sp = &stage[r * 20 + cs];
                float o[8];
#pragma unroll
                for (int c = 0; c < 8; c++) {
                    float v = sp[c];
                    if (BR) v = fmaxf(v + bias[gn + c], 0.f);
                    o[c] = v;
                }
                uint4 pk;
                __half2 p0 = __floats2half2_rn(o[0], o[1]);
                __half2 p1 = __floats2half2_rn(o[2], o[3]);
                __half2 p2 = __floats2half2_rn(o[4], o[5]);
                __half2 p3 = __floats2half2_rn(o[6], o[7]);
                pk.x = *(unsigned*)&p0; pk.y = *(unsigned*)&p1;
                pk.z = *(unsigned*)&p2; pk.w = *(unsigned*)&p3;
                *(uint4*)&C[(size_t)gm * N + gn] = pk;
            }
            __syncwarp();
        }
    }
}

// ---------------- final projection 512 -> 3 (half input) ----------------
__global__ void __launch_bounds__(256) k_out3(const __half* __restrict__ h,
                                              const float* __restrict__ Wc,
                                              const float* __restrict__ bc,
                                              float* __restrict__ out) {
    __shared__ float wc[512 * 3];
    for (int i = threadIdx.x; i < 512 * 3; i += blockDim.x) wc[i] = Wc[i];
    __syncthreads();
    int gw   = (blockIdx.x * blockDim.x + threadIdx.x) >> 5;
    int lane = threadIdx.x & 31;
    if (gw >= NV) return;
    float a0 = 0.f, a1 = 0.f, a2 = 0.f;
    const __half2* hp = (const __half2*)(h + (size_t)gw * 512);
#pragma unroll
    for (int i = 0; i < 8; i++) {
        int k2 = lane + 32 * i;              // half2 index: cols 2k2, 2k2+1
        float2 hv = __half22float2(hp[k2]);
        int k = k2 * 2;
        a0 += hv.x * wc[k * 3 + 0] + hv.y * wc[(k + 1) * 3 + 0];
        a1 += hv.x * wc[k * 3 + 1] + hv.y * wc[(k + 1) * 3 + 1];
        a2 += hv.x * wc[k * 3 + 2] + hv.y * wc[(k + 1) * 3 + 2];
    }
#pragma unroll
    for (int o = 16; o; o >>= 1) {
        a0 += __shfl_xor_sync(0xFFFFFFFFu, a0, o);
        a1 += __shfl_xor_sync(0xFFFFFFFFu, a1, o);
        a2 += __shfl_xor_sync(0xFFFFFFFFu, a2, o);
    }
    if (lane == 0) {
        out[gw * 3 + 0] = a0 + bc[0];
        out[gw * 3 + 1] = a1 + bc[1];
        out[gw * 3 + 2] = a2 + bc[2];
    }
}

// ---------------- launch ----------------
extern "C" void kernel_launch(void* const* d_in, const int* in_sizes, int n_in,
                              void* d_out, int out_size) {
    const float* x  = (const float*)d_in[0];
    const void*  ei = d_in[1];
    const float* W1 = (const float*)d_in[2];
    const float* b1 = (const float*)d_in[3];
    const float* W2 = (const float*)d_in[4];
    const float* b2 = (const float*)d_in[5];
    const float* W3 = (const float*)d_in[6];
    const float* b3 = (const float*)d_in[7];
    const float* Wi = (const float*)d_in[8];
    const float* bi = (const float*)d_in[9];
    const float* Wc = (const float*)d_in[10];
    const float* bc = (const float*)d_in[11];
    float* out = (float*)d_out;

    __half *pXh, *pAh, *pHh, *pY1, *pY2, *pW1h, *pW2h, *pW3h, *pWih;
    cudaGetSymbolAddress((void**)&pXh,  g_xh);
    cudaGetSymbolAddress((void**)&pAh,  g_ah);
    cudaGetSymbolAddress((void**)&pHh,  g_hh);
    cudaGetSymbolAddress((void**)&pY1,  g_y1);
    cudaGetSymbolAddress((void**)&pY2,  g_y2);
    cudaGetSymbolAddress((void**)&pW1h, g_w1h);
    cudaGetSymbolAddress((void**)&pW2h, g_w2h);
    cudaGetSymbolAddress((void**)&pW3h, g_w3h);
    cudaGetSymbolAddress((void**)&pWih, g_wih);

    const int TB  = 256;
    const int NPB = (NE / 2 + TB - 1) / TB;
    const int AGB = (NV + 7) / 8;

    // idx0..2: init, W1->half, x->half
    k_init_detect<<<NBLK, TB>>>((const int*)ei);
    k_f2h<<<(128 * 128 / 4 + TB - 1) / TB, TB>>>((const float4*)W1, (uint2*)pW1h,
                                                 128 * 128 / 4);
    k_f2h<<<(NV * 128 / 4 + TB - 1) / TB, TB>>>((const float4*)x, (uint2*)pXh,
                                                NV * 128 / 4);
    // idx3: PROFILED — fp16 tensor GEMM L1 (Xh @ W1h, raw)
    k_hgemm<false><<<dim3(1, MT128), 256>>>(pXh, pW1h, b1, pAh, NV, 128, 128);

    // preprocessing + remaining weight conversions
    k_hist<<<NPB, TB>>>(ei);
    k_reduce<<<NBLK, TB>>>();
    k_scanb<<<1, 512>>>();
    k_scatter<<<NBLK, TB>>>();
    k_fill<<<NPB, TB>>>(ei);
    k_f2h<<<(128 * 128 / 4 + TB - 1) / TB, TB>>>((const float4*)W2, (uint2*)pW2h,
                                                 128 * 128 / 4);
    k_f2h<<<(128 * 512 / 4 + TB - 1) / TB, TB>>>((const float4*)W3, (uint2*)pW3h,
                                                 128 * 512 / 4);
    k_f2h<<<(512 * 512 / 4 + TB - 1) / TB, TB>>>((const float4*)Wi, (uint2*)pWih,
                                                 512 * 512 / 4);

    // L1: aggregate(XW1) + b1, relu
    k_aggh<true><<<AGB, TB>>>((const uint2*)pAh, (uint2*)pHh, (const float4*)b1);
    // L2: project then aggregate (+b2, relu)
    k_hgemm<false><<<dim3(1, MT128), 256>>>(pHh, pW2h, b2, pAh, NV, 128, 128);
    k_aggh<true><<<AGB, TB>>>((const uint2*)pAh, (uint2*)pHh, (const float4*)b2);
    // L3: aggregate (plain) then project 128->512 (+b3, relu)
    k_aggh<false><<<AGB, TB>>>((const uint2*)pHh, (uint2*)pAh, (const float4*)b3);
    k_hgemm<true><<<dim3(4, MT128), 256>>>(pAh, pW3h, b3, pY1, NV, 128, 512);
    // MLP 512->512 (+bi, relu)
    k_hgemm<true><<<dim3(4, MT128), 256>>>(pY1, pWih, bi, pY2, NV, 512, 512);
    // classifier
    k_out3<<<(NV * 32 + TB - 1) / TB, TB>>>(pY2, Wc, bc, out);
}

// round 15
// speedup vs baseline: 2.2147x; 1.0127x over previous
#include <cuda_runtime.h>
#include <cuda_fp16.h>
#include <cstdint>
#include <mma.h>
#include <math.h>

using namespace nvcuda;

#define NV 100000
#define NE 3200000
#define NBLK 391          // ceil(NV/256)
#define MT128 782         // ceil(NV/128)

// ---------------- scratch (device globals: allocation-free) ----------------
__device__ int    g_is64;
__device__ float  g_dinv[NV];
__device__ int    g_indeg[NV];
__device__ int    g_rowptr[NV + 1];
__device__ int    g_cursor[NV];
__device__ int    g_bsum[NBLK];
__device__ int    g_boff[NBLK];
__device__ int    g_col[NE];
__device__ __half g_xh[NV * 128];
__device__ __half g_ah[NV * 128];
__device__ __half g_hh[NV * 128];
__device__ __half g_y1[NV * 512];
__device__ __half g_y2[NV * 512];
__device__ __half g_w1h[128 * 128];
__device__ __half g_w2h[128 * 128];
__device__ __half g_w3h[128 * 512];
__device__ __half g_wih[512 * 512];

// ---------------- half<->float helpers ----------------
__device__ __forceinline__ float4 h4tof4(uint2 v) {
    __half2 h0 = *(__half2*)&v.x;
    __half2 h1 = *(__half2*)&v.y;
    float2 f0 = __half22float2(h0), f1 = __half22float2(h1);
    return make_float4(f0.x, f0.y, f1.x, f1.y);
}
__device__ __forceinline__ uint2 f4toh4(float4 f) {
    __half2 h0 = __floats2half2_rn(f.x, f.y);
    __half2 h1 = __floats2half2_rn(f.z, f.w);
    uint2 o;
    o.x = *(unsigned*)&h0;
    o.y = *(unsigned*)&h1;
    return o;
}

__global__ void k_f2h(const float4* __restrict__ src, uint2* __restrict__ dst,
                      int n4) {
    int i = blockIdx.x * blockDim.x + threadIdx.x;
    if (i >= n4) return;
    dst[i] = f4toh4(src[i]);
}

// ---------------- cp.async helpers ----------------
__device__ __forceinline__ uint32_t smem_u32(const void* p) {
    return (uint32_t)__cvta_generic_to_shared(p);
}
__device__ __forceinline__ void cp16_sh(uint32_t dst, const void* src, bool pred) {
    int sz = pred ? 16 : 0;
    asm volatile("cp.async.cg.shared.global [%0], [%1], 16, %2;"
                 :: "r"(dst), "l"(src), "r"(sz));
}
__device__ __forceinline__ void cp_commit() {
    asm volatile("cp.async.commit_group;");
}
template <int N>
__device__ __forceinline__ void cp_wait() {
    asm volatile("cp.async.wait_group %0;" :: "n"(N));
}

// ---------------- init + dtype detection (fused) ---------------------------
__global__ void k_init_detect(const int* ei32) {
    int i = blockIdx.x * blockDim.x + threadIdx.x;
    if (i < NV) g_indeg[i] = 0;
    if (blockIdx.x == 0) {
        __shared__ int nz;
        if (threadIdx.x == 0) nz = 0;
        __syncthreads();
        int c = 0;
        for (int k = threadIdx.x; k < 2048; k += blockDim.x)
            if (ei32[2 * k + 1] != 0) c = 1;
        if (c) atomicExch(&nz, 1);
        __syncthreads();
        if (threadIdx.x == 0) g_is64 = (nz == 0) ? 1 : 0;
    }
}

// ---------------- degree histogram (2 edges / thread) ----------------------
__global__ void k_hist(const void* ei) {
    int e = blockIdx.x * blockDim.x + threadIdx.x;
    if (e * 2 >= NE) return;
    int d0, d1;
    if (g_is64) {
        longlong2 v = ((const longlong2*)ei)[NE / 2 + e];
        d0 = (int)v.x; d1 = (int)v.y;
    } else {
        int2 v = ((const int2*)ei)[NE / 2 + e];
        d0 = v.x; d1 = v.y;
    }
    atomicAdd(&g_indeg[d0], 1);
    atomicAdd(&g_indeg[d1], 1);
}

// ---------------- 3-phase scan ----------------
__global__ void __launch_bounds__(256) k_reduce() {
    int i = blockIdx.x * 256 + threadIdx.x;
    int v = (i < NV) ? g_indeg[i] : 0;
#pragma unroll
    for (int o = 16; o; o >>= 1) v += __shfl_xor_sync(0xFFFFFFFFu, v, o);
    __shared__ int ws[8];
    if ((threadIdx.x & 31) == 0) ws[threadIdx.x >> 5] = v;
    __syncthreads();
    if (threadIdx.x == 0) {
        int s = 0;
#pragma unroll
        for (int j = 0; j < 8; j++) s += ws[j];
        g_bsum[blockIdx.x] = s;
    }
}

__global__ void __launch_bounds__(512) k_scanb() {
    int t = threadIdx.x;
    int v = (t < NBLK) ? g_bsum[t] : 0;
    int incl = v;
#pragma unroll
    for (int o = 1; o < 32; o <<= 1) {
        int n = __shfl_up_sync(0xFFFFFFFFu, incl, o);
        if ((t & 31) >= o) incl += n;
    }
    __shared__ int ws[16];
    if ((t & 31) == 31) ws[t >> 5] = incl;
    __syncthreads();
    if (t == 0) {
        int run = 0;
#pragma unroll
        for (int j = 0; j < 16; j++) { int x = ws[j]; ws[j] = run; run += x; }
    }
    __syncthreads();
    if (t < NBLK) g_boff[t] = incl - v + ws[t >> 5];
}

__global__ void __launch_bounds__(256) k_scatter() {
    int b = blockIdx.x, t = threadIdx.x;
    int i = b * 256 + t;
    int v = (i < NV) ? g_indeg[i] : 0;
    int incl = v;
#pragma unroll
    for (int o = 1; o < 32; o <<= 1) {
        int n = __shfl_up_sync(0xFFFFFFFFu, incl, o);
        if ((t & 31) >= o) incl += n;
    }
    __shared__ int ws[8];
    if ((t & 31) == 31) ws[t >> 5] = incl;
    __syncthreads();
    if (t == 0) {
        int run = 0;
#pragma unroll
        for (int j = 0; j < 8; j++) { int x = ws[j]; ws[j] = run; run += x; }
    }
    __syncthreads();
    int ex = incl - v + ws[t >> 5] + g_boff[b];
    if (i < NV) {
        g_rowptr[i] = ex;
        g_cursor[i] = ex;
        g_dinv[i]   = rsqrtf((float)(v + 1));
        if (i == NV - 1) g_rowptr[NV] = ex + v;
    }
}

__global__ void k_fill(const void* ei) {
    int e = blockIdx.x * blockDim.x + threadIdx.x;
    if (e * 2 >= NE) return;
    int s0, s1, d0, d1;
    if (g_is64) {
        longlong2 sv = ((const longlong2*)ei)[e];
        longlong2 dv = ((const longlong2*)ei)[NE / 2 + e];
        s0 = (int)sv.x; s1 = (int)sv.y;
        d0 = (int)dv.x; d1 = (int)dv.y;
    } else {
        int2 sv = ((const int2*)ei)[e];
        int2 dv = ((const int2*)ei)[NE / 2 + e];
        s0 = sv.x; s1 = sv.y;
        d0 = dv.x; d1 = dv.y;
    }
    int p0 = atomicAdd(&g_cursor[d0], 1);
    g_col[p0] = s0;
    int p1 = atomicAdd(&g_cursor[d1], 1);
    g_col[p1] = s1;
}

// ---------------- aggregation: warp/node, half4/lane, fp32 accumulate ------
template <bool BR>
__global__ void __launch_bounds__(256) k_aggh(const uint2* __restrict__ xin,
                                              uint2* __restrict__ xout,
                                              const float4* __restrict__ bias4) {
    int w = (blockIdx.x << 3) + (threadIdx.x >> 5);
    if (w >= NV) return;
    int lane = threadIdx.x & 31;
    float dv = g_dinv[w];
    float4 xv = h4tof4(xin[(size_t)w * 32 + lane]);
    float dvv = dv * dv;
    float4 acc;
    acc.x = dvv * xv.x; acc.y = dvv * xv.y; acc.z = dvv * xv.z; acc.w = dvv * xv.w;
    int e  = g_rowptr[w];
    int e1 = g_rowptr[w + 1];
    for (; e + 3 < e1; e += 4) {
        int s0 = g_col[e],     s1 = g_col[e + 1];
        int s2 = g_col[e + 2], s3 = g_col[e + 3];
        float w0 = dv * g_dinv[s0], w1 = dv * g_dinv[s1];
        float w2 = dv * g_dinv[s2], w3 = dv * g_dinv[s3];
        float4 v0 = h4tof4(xin[(size_t)s0 * 32 + lane]);
        float4 v1 = h4tof4(xin[(size_t)s1 * 32 + lane]);
        float4 v2 = h4tof4(xin[(size_t)s2 * 32 + lane]);
        float4 v3 = h4tof4(xin[(size_t)s3 * 32 + lane]);
        acc.x += w0 * v0.x + w1 * v1.x + w2 * v2.x + w3 * v3.x;
        acc.y += w0 * v0.y + w1 * v1.y + w2 * v2.y + w3 * v3.y;
        acc.z += w0 * v0.z + w1 * v1.z + w2 * v2.z + w3 * v3.z;
        acc.w += w0 * v0.w + w1 * v1.w + w2 * v2.w + w3 * v3.w;
    }
    for (; e < e1; e++) {
        int s = g_col[e];
        float ws = dv * g_dinv[s];
        float4 v = h4tof4(xin[(size_t)s * 32 + lane]);
        acc.x += ws * v.x; acc.y += ws * v.y; acc.z += ws * v.z; acc.w += ws * v.w;
    }
    if (BR) {
        float4 b = bias4[lane];
        acc.x = fmaxf(acc.x + b.x, 0.f);
        acc.y = fmaxf(acc.y + b.y, 0.f);
        acc.z = fmaxf(acc.z + b.z, 0.f);
        acc.w = fmaxf(acc.w + b.w, 0.f);
    }
    xout[(size_t)w * 32 + lane] = f4toh4(acc);
}

// ---------------- fp16 tensor GEMM: 64x64 warp tile, 4 warps/CTA -----------
// Block tile 128x128, BK=32, 2-stage cp.async, fp32 accumulate.
constexpr int HBK  = 32;
constexpr int HLDA = HBK + 8;     // 40 halves
constexpr int HLDB = 128 + 8;     // 136 halves
constexpr int HASZ = 128 * HLDA;  // 5120 halves / stage
constexpr int HBSZ = HBK * HLDB;  // 4352 halves / stage

template <bool BR>
__global__ void __launch_bounds__(128, 2) k_hgemm(const __half* __restrict__ A,
                                                  const __half* __restrict__ B,
                                                  const float* __restrict__ bias,
                                                  __half* __restrict__ C,
                                                  int M, int K, int N) {
    __shared__ __half sA[2 * HASZ];
    __shared__ __half sB[2 * HBSZ];

    int tid  = threadIdx.x;
    int warp = tid >> 5;
    int lane = tid & 31;
    int m0 = blockIdx.y << 7, n0 = blockIdx.x << 7;
    int wm = warp & 1, wn = warp >> 1;   // 2 M x 2 N, warp tile 64x64

    wmma::fragment<wmma::accumulator, 16, 16, 16, float> acc[4][4];
#pragma unroll
    for (int i = 0; i < 4; i++)
#pragma unroll
        for (int j = 0; j < 4; j++) wmma::fill_fragment(acc[i][j], 0.0f);

    int KT = K / HBK;

    auto load_tile = [&](int t, int buf) {
        int k0 = t * HBK;
        // A tile 128x32 halves = 512 x 16B chunks, 4/thread
#pragma unroll
        for (int i = 0; i < 4; i++) {
            int idx = tid + 128 * i;
            int r = idx >> 2, c = (idx & 3) * 8;
            bool ok = (m0 + r) < M;
            cp16_sh(smem_u32(&sA[buf * HASZ + r * HLDA + c]),
                    A + (size_t)(m0 + r) * K + k0 + c, ok);
        }
        // B tile 32x128 halves = 512 x 16B chunks, 4/thread
#pragma unroll
        for (int i = 0; i < 4; i++) {
            int idx = tid + 128 * i;
            int r = idx >> 4, c = (idx & 15) * 8;
            cp16_sh(smem_u32(&sB[buf * HBSZ + r * HLDB + c]),
                    B + (size_t)(k0 + r) * N + n0 + c, true);
        }
        cp_commit();
    };

    load_tile(0, 0);
    for (int t = 0; t < KT; t++) {
        int cur = t & 1;
        if (t + 1 < KT) {
            load_tile(t + 1, cur ^ 1);
            cp_wait<1>();
        } else {
            cp_wait<0>();
        }
        __syncthreads();
        __half* Ab = sA + cur * HASZ;
        __half* Bb = sB + cur * HBSZ;
#pragma unroll
        for (int kk = 0; kk < HBK; kk += 16) {
            wmma::fragment<wmma::matrix_a, 16, 16, 16, __half, wmma::row_major> af[4];
            wmma::fragment<wmma::matrix_b, 16, 16, 16, __half, wmma::row_major> bf[4];
#pragma unroll
            for (int i = 0; i < 4; i++)
                wmma::load_matrix_sync(af[i], &Ab[(wm * 64 + i * 16) * HLDA + kk],
                                       HLDA);
#pragma unroll
            for (int j = 0; j < 4; j++)
                wmma::load_matrix_sync(bf[j], &Bb[kk * HLDB + wn * 64 + j * 16],
                                       HLDB);
#pragma unroll
            for (int i = 0; i < 4; i++)
#pragma unroll
                for (int j = 0; j < 4; j++)
                    wmma::mma_sync(acc[i][j], af[i], bf[j], acc[i][j]);
        }
        __syncthreads();
    }

    // epilogue: per-warp fp32 stage (16x20) in reused sA, bias+relu, half out
    float* stage = reinterpret_cast<float*>(sA) + warp * 320;
#pragma unroll
    for (int i = 0; i < 4; i++) {
#pragma unroll
        for (int j = 0; j < 4; j++) {
            wmma::store_matrix_sync(stage, acc[i][j], 20, wmma::mem_row_major);
            __syncwarp();
            int r  = lane >> 1;
            int cs = (lane & 1) * 8;
            int gm = m0 + wm * 64 + i * 16 + r;
            int gn = n0 + wn * 64 + j * 16 + cs;
            if (gm < M) {
                const float* sp = &stage[r * 20 + cs];
                float o[8];
#pragma unroll
                for (int c = 0; c < 8; c++) {
                    float v = sp[c];
                    if (BR) v = fmaxf(v + bias[gn + c], 0.f);
                    o[c] = v;
                }
                uint4 pk;
                __half2 p0 = __floats2half2_rn(o[0], o[1]);
                __half2 p1 = __floats2half2_rn(o[2], o[3]);
                __half2 p2 = __floats2half2_rn(o[4], o[5]);
                __half2 p3 = __floats2half2_rn(o[6], o[7]);
                pk.x = *(unsigned*)&p0; pk.y = *(unsigned*)&p1;
                pk.z = *(unsigned*)&p2; pk.w = *(unsigned*)&p3;
                *(uint4*)&C[(size_t)gm * N + gn] = pk;
            }
            __syncwarp();
        }
    }
}

// ---------------- final projection 512 -> 3 (half input) ----------------
__global__ void __launch_bounds__(256) k_out3(const __half* __restrict__ h,
                                              const float* __restrict__ Wc,
                                              const float* __restrict__ bc,
                                              float* __restrict__ out) {
    __shared__ float wc[512 * 3];
    for (int i = threadIdx.x; i < 512 * 3; i += blockDim.x) wc[i] = Wc[i];
    __syncthreads();
    int gw   = (blockIdx.x * blockDim.x + threadIdx.x) >> 5;
    int lane = threadIdx.x & 31;
    if (gw >= NV) return;
    float a0 = 0.f, a1 = 0.f, a2 = 0.f;
    const __half2* hp = (const __half2*)(h + (size_t)gw * 512);
#pragma unroll
    for (int i = 0; i < 8; i++) {
        int k2 = lane + 32 * i;
        float2 hv = __half22float2(hp[k2]);
        int k = k2 * 2;
        a0 += hv.x * wc[k * 3 + 0] + hv.y * wc[(k + 1) * 3 + 0];
        a1 += hv.x * wc[k * 3 + 1] + hv.y * wc[(k + 1) * 3 + 1];
        a2 += hv.x * wc[k * 3 + 2] + hv.y * wc[(k + 1) * 3 + 2];
    }
#pragma unroll
    for (int o = 16; o; o >>= 1) {
        a0 += __shfl_xor_sync(0xFFFFFFFFu, a0, o);
        a1 += __shfl_xor_sync(0xFFFFFFFFu, a1, o);
        a2 += __shfl_xor_sync(0xFFFFFFFFu, a2, o);
    }
    if (lane == 0) {
        out[gw * 3 + 0] = a0 + bc[0];
        out[gw * 3 + 1] = a1 + bc[1];
        out[gw * 3 + 2] = a2 + bc[2];
    }
}

// ---------------- launch ----------------
extern "C" void kernel_launch(void* const* d_in, const int* in_sizes, int n_in,
                              void* d_out, int out_size) {
    const float* x  = (const float*)d_in[0];
    const void*  ei = d_in[1];
    const float* W1 = (const float*)d_in[2];
    const float* b1 = (const float*)d_in[3];
    const float* W2 = (const float*)d_in[4];
    const float* b2 = (const float*)d_in[5];
    const float* W3 = (const float*)d_in[6];
    const float* b3 = (const float*)d_in[7];
    const float* Wi = (const float*)d_in[8];
    const float* bi = (const float*)d_in[9];
    const float* Wc = (const float*)d_in[10];
    const float* bc = (const float*)d_in[11];
    float* out = (float*)d_out;

    __half *pXh, *pAh, *pHh, *pY1, *pY2, *pW1h, *pW2h, *pW3h, *pWih;
    cudaGetSymbolAddress((void**)&pXh,  g_xh);
    cudaGetSymbolAddress((void**)&pAh,  g_ah);
    cudaGetSymbolAddress((void**)&pHh,  g_hh);
    cudaGetSymbolAddress((void**)&pY1,  g_y1);
    cudaGetSymbolAddress((void**)&pY2,  g_y2);
    cudaGetSymbolAddress((void**)&pW1h, g_w1h);
    cudaGetSymbolAddress((void**)&pW2h, g_w2h);
    cudaGetSymbolAddress((void**)&pW3h, g_w3h);
    cudaGetSymbolAddress((void**)&pWih, g_wih);

    const int TB  = 256;
    const int NPB = (NE / 2 + TB - 1) / TB;
    const int AGB = (NV + 7) / 8;

    // idx0..2: init, W1->half, x->half
    k_init_detect<<<NBLK, TB>>>((const int*)ei);
    k_f2h<<<(128 * 128 / 4 + TB - 1) / TB, TB>>>((const float4*)W1, (uint2*)pW1h,
                                                 128 * 128 / 4);
    k_f2h<<<(NV * 128 / 4 + TB - 1) / TB, TB>>>((const float4*)x, (uint2*)pXh,
                                                NV * 128 / 4);
    // idx3: PROFILED — fp16 tensor GEMM L1 (Xh @ W1h, raw)
    k_hgemm<false><<<dim3(1, MT128), 128>>>(pXh, pW1h, b1, pAh, NV, 128, 128);

    // preprocessing + remaining weight conversions
    k_hist<<<NPB, TB>>>(ei);
    k_reduce<<<NBLK, TB>>>();
    k_scanb<<<1, 512>>>();
    k_scatter<<<NBLK, TB>>>();
    k_fill<<<NPB, TB>>>(ei);
    k_f2h<<<(128 * 128 / 4 + TB - 1) / TB, TB>>>((const float4*)W2, (uint2*)pW2h,
                                                 128 * 128 / 4);
    k_f2h<<<(128 * 512 / 4 + TB - 1) / TB, TB>>>((const float4*)W3, (uint2*)pW3h,
                                                 128 * 512 / 4);
    k_f2h<<<(512 * 512 / 4 + TB - 1) / TB, TB>>>((const float4*)Wi, (uint2*)pWih,
                                                 512 * 512 / 4);

    // L1: aggregate(XW1) + b1, relu
    k_aggh<true><<<AGB, TB>>>((const uint2*)pAh, (uint2*)pHh, (const float4*)b1);
    // L2: project then aggregate (+b2, relu)
    k_hgemm<false><<<dim3(1, MT128), 128>>>(pHh, pW2h, b2, pAh, NV, 128, 128);
    k_aggh<true><<<AGB, TB>>>((const uint2*)pAh, (uint2*)pHh, (const float4*)b2);
    // L3: aggregate (plain) then project 128->512 (+b3, relu)
    k_aggh<false><<<AGB, TB>>>((const uint2*)pHh, (uint2*)pAh, (const float4*)b3);
    k_hgemm<true><<<dim3(4, MT128), 128>>>(pAh, pW3h, b3, pY1, NV, 128, 512);
    // MLP 512->512 (+bi, relu)
    k_hgemm<true><<<dim3(4, MT128), 128>>>(pY1, pWih, bi, pY2, NV, 512, 512);
    // classifier
    k_out3<<<(NV * 32 + TB - 1) / TB, TB>>>(pY2, Wc, bc, out);
}

// round 16
// speedup vs baseline: 2.2208x; 1.0028x over previous
#include <cuda_runtime.h>
#include <cuda_fp16.h>
#include <cstdint>
#include <mma.h>
#include <math.h>

using namespace nvcuda;

#define NV 100000
#define NE 3200000
#define NBLK 391          // ceil(NV/256)
#define MT128 782         // ceil(NV/128)

// ---------------- scratch (device globals: allocation-free) ----------------
__device__ int    g_is64;
__device__ float  g_dinv[NV];
__device__ int    g_indeg[NV];
__device__ int    g_rowptr[NV + 1];
__device__ int    g_cursor[NV];
__device__ int    g_bsum[NBLK];
__device__ int    g_boff[NBLK];
__device__ int    g_col[NE];
__device__ __half g_xh[NV * 128];
__device__ __half g_ah[NV * 128];
__device__ __half g_hh[NV * 128];
__device__ __half g_y1[NV * 512];
__device__ __half g_y2[NV * 512];
__device__ __half g_w1h[128 * 128];
__device__ __half g_w2h[128 * 128];
__device__ __half g_w3h[128 * 512];
__device__ __half g_wih[512 * 512];

// ---------------- half<->float helpers ----------------
__device__ __forceinline__ float4 h4tof4(uint2 v) {
    __half2 h0 = *(__half2*)&v.x;
    __half2 h1 = *(__half2*)&v.y;
    float2 f0 = __half22float2(h0), f1 = __half22float2(h1);
    return make_float4(f0.x, f0.y, f1.x, f1.y);
}
__device__ __forceinline__ uint2 f4toh4(float4 f) {
    __half2 h0 = __floats2half2_rn(f.x, f.y);
    __half2 h1 = __floats2half2_rn(f.z, f.w);
    uint2 o;
    o.x = *(unsigned*)&h0;
    o.y = *(unsigned*)&h1;
    return o;
}

__global__ void k_f2h(const float4* __restrict__ src, uint2* __restrict__ dst,
                      int n4) {
    int i = blockIdx.x * blockDim.x + threadIdx.x;
    if (i >= n4) return;
    dst[i] = f4toh4(src[i]);
}

// ---------------- cp.async helpers ----------------
__device__ __forceinline__ uint32_t smem_u32(const void* p) {
    return (uint32_t)__cvta_generic_to_shared(p);
}
__device__ __forceinline__ void cp16_sh(uint32_t dst, const void* src, bool pred) {
    int sz = pred ? 16 : 0;
    asm volatile("cp.async.cg.shared.global [%0], [%1], 16, %2;"
                 :: "r"(dst), "l"(src), "r"(sz));
}
__device__ __forceinline__ void cp_commit() {
    asm volatile("cp.async.commit_group;");
}
template <int N>
__device__ __forceinline__ void cp_wait() {
    asm volatile("cp.async.wait_group %0;" :: "n"(N));
}

// ---------------- init + dtype detection (fused) ---------------------------
__global__ void k_init_detect(const int* ei32) {
    int i = blockIdx.x * blockDim.x + threadIdx.x;
    if (i < NV) g_indeg[i] = 0;
    if (blockIdx.x == 0) {
        __shared__ int nz;
        if (threadIdx.x == 0) nz = 0;
        __syncthreads();
        int c = 0;
        for (int k = threadIdx.x; k < 2048; k += blockDim.x)
            if (ei32[2 * k + 1] != 0) c = 1;
        if (c) atomicExch(&nz, 1);
        __syncthreads();
        if (threadIdx.x == 0) g_is64 = (nz == 0) ? 1 : 0;
    }
}

// ---------------- degree histogram (2 edges / thread) ----------------------
__global__ void k_hist(const void* ei) {
    int e = blockIdx.x * blockDim.x + threadIdx.x;
    if (e * 2 >= NE) return;
    int d0, d1;
    if (g_is64) {
        longlong2 v = ((const longlong2*)ei)[NE / 2 + e];
        d0 = (int)v.x; d1 = (int)v.y;
    } else {
        int2 v = ((const int2*)ei)[NE / 2 + e];
        d0 = v.x; d1 = v.y;
    }
    atomicAdd(&g_indeg[d0], 1);
    atomicAdd(&g_indeg[d1], 1);
}

// ---------------- 3-phase scan ----------------
__global__ void __launch_bounds__(256) k_reduce() {
    int i = blockIdx.x * 256 + threadIdx.x;
    int v = (i < NV) ? g_indeg[i] : 0;
#pragma unroll
    for (int o = 16; o; o >>= 1) v += __shfl_xor_sync(0xFFFFFFFFu, v, o);
    __shared__ int ws[8];
    if ((threadIdx.x & 31) == 0) ws[threadIdx.x >> 5] = v;
    __syncthreads();
    if (threadIdx.x == 0) {
        int s = 0;
#pragma unroll
        for (int j = 0; j < 8; j++) s += ws[j];
        g_bsum[blockIdx.x] = s;
    }
}

__global__ void __launch_bounds__(512) k_scanb() {
    int t = threadIdx.x;
    int v = (t < NBLK) ? g_bsum[t] : 0;
    int incl = v;
#pragma unroll
    for (int o = 1; o < 32; o <<= 1) {
        int n = __shfl_up_sync(0xFFFFFFFFu, incl, o);
        if ((t & 31) >= o) incl += n;
    }
    __shared__ int ws[16];
    if ((t & 31) == 31) ws[t >> 5] = incl;
    __syncthreads();
    if (t == 0) {
        int run = 0;
#pragma unroll
        for (int j = 0; j < 16; j++) { int x = ws[j]; ws[j] = run; run += x; }
    }
    __syncthreads();
    if (t < NBLK) g_boff[t] = incl - v + ws[t >> 5];
}

__global__ void __launch_bounds__(256) k_scatter() {
    int b = blockIdx.x, t = threadIdx.x;
    int i = b * 256 + t;
    int v = (i < NV) ? g_indeg[i] : 0;
    int incl = v;
#pragma unroll
    for (int o = 1; o < 32; o <<= 1) {
        int n = __shfl_up_sync(0xFFFFFFFFu, incl, o);
        if ((t & 31) >= o) incl += n;
    }
    __shared__ int ws[8];
    if ((t & 31) == 31) ws[t >> 5] = incl;
    __syncthreads();
    if (t == 0) {
        int run = 0;
#pragma unroll
        for (int j = 0; j < 8; j++) { int x = ws[j]; ws[j] = run; run += x; }
    }
    __syncthreads();
    int ex = incl - v + ws[t >> 5] + g_boff[b];
    if (i < NV) {
        g_rowptr[i] = ex;
        g_cursor[i] = ex;
        g_dinv[i]   = rsqrtf((float)(v + 1));
        if (i == NV - 1) g_rowptr[NV] = ex + v;
    }
}

__global__ void k_fill(const void* ei) {
    int e = blockIdx.x * blockDim.x + threadIdx.x;
    if (e * 2 >= NE) return;
    int s0, s1, d0, d1;
    if (g_is64) {
        longlong2 sv = ((const longlong2*)ei)[e];
        longlong2 dv = ((const longlong2*)ei)[NE / 2 + e];
        s0 = (int)sv.x; s1 = (int)sv.y;
        d0 = (int)dv.x; d1 = (int)dv.y;
    } else {
        int2 sv = ((const int2*)ei)[e];
        int2 dv = ((const int2*)ei)[NE / 2 + e];
        s0 = sv.x; s1 = sv.y;
        d0 = dv.x; d1 = dv.y;
    }
    int p0 = atomicAdd(&g_cursor[d0], 1);
    g_col[p0] = s0;
    int p1 = atomicAdd(&g_cursor[d1], 1);
    g_col[p1] = s1;
}

// ---------------- aggregation: warp/node, half4/lane, fp32 accumulate ------
template <bool BR>
__global__ void __launch_bounds__(256) k_aggh(const uint2* __restrict__ xin,
                                              uint2* __restrict__ xout,
                                              const float4* __restrict__ bias4) {
    int w = (blockIdx.x << 3) + (threadIdx.x >> 5);
    if (w >= NV) return;
    int lane = threadIdx.x & 31;
    float dv = g_dinv[w];
    float4 xv = h4tof4(xin[(size_t)w * 32 + lane]);
    float dvv = dv * dv;
    float4 acc;
    acc.x = dvv * xv.x; acc.y = dvv * xv.y; acc.z = dvv * xv.z; acc.w = dvv * xv.w;
    int e  = g_rowptr[w];
    int e1 = g_rowptr[w + 1];
    for (; e + 3 < e1; e += 4) {
        int s0 = g_col[e],     s1 = g_col[e + 1];
        int s2 = g_col[e + 2], s3 = g_col[e + 3];
        float w0 = dv * g_dinv[s0], w1 = dv * g_dinv[s1];
        float w2 = dv * g_dinv[s2], w3 = dv * g_dinv[s3];
        float4 v0 = h4tof4(xin[(size_t)s0 * 32 + lane]);
        float4 v1 = h4tof4(xin[(size_t)s1 * 32 + lane]);
        float4 v2 = h4tof4(xin[(size_t)s2 * 32 + lane]);
        float4 v3 = h4tof4(xin[(size_t)s3 * 32 + lane]);
        acc.x += w0 * v0.x + w1 * v1.x + w2 * v2.x + w3 * v3.x;
        acc.y += w0 * v0.y + w1 * v1.y + w2 * v2.y + w3 * v3.y;
        acc.z += w0 * v0.z + w1 * v1.z + w2 * v2.z + w3 * v3.z;
        acc.w += w0 * v0.w + w1 * v1.w + w2 * v2.w + w3 * v3.w;
    }
    for (; e < e1; e++) {
        int s = g_col[e];
        float ws = dv * g_dinv[s];
        float4 v = h4tof4(xin[(size_t)s * 32 + lane]);
        acc.x += ws * v.x; acc.y += ws * v.y; acc.z += ws * v.z; acc.w += ws * v.w;
    }
    if (BR) {
        float4 b = bias4[lane];
        acc.x = fmaxf(acc.x + b.x, 0.f);
        acc.y = fmaxf(acc.y + b.y, 0.f);
        acc.z = fmaxf(acc.z + b.z, 0.f);
        acc.w = fmaxf(acc.w + b.w, 0.f);
    }
    xout[(size_t)w * 32 + lane] = f4toh4(acc);
}

// ---------------- fp16 tensor GEMM: 64x64 warp tile, 3-stage pipeline ------
// Block tile 128x128, BK=32, 3-stage cp.async (dynamic smem), fp32 accum.
constexpr int HBK  = 32;
constexpr int HLDA = HBK + 8;     // 40 halves
constexpr int HLDB = 128 + 8;     // 136 halves
constexpr int HASZ = 128 * HLDA;  // 5120 halves / stage
constexpr int HBSZ = HBK * HLDB;  // 4352 halves / stage
constexpr int HSMEM_BYTES = 3 * (HASZ + HBSZ) * 2;   // 56832 B

template <bool BR>
__global__ void __launch_bounds__(128, 2) k_hgemm(const __half* __restrict__ A,
                                                  const __half* __restrict__ B,
                                                  const float* __restrict__ bias,
                                                  __half* __restrict__ C,
                                                  int M, int K, int N) {
    extern __shared__ __half dsm[];
    __half* sA = dsm;               // 3 stages
    __half* sB = dsm + 3 * HASZ;    // 3 stages

    int tid  = threadIdx.x;
    int warp = tid >> 5;
    int lane = tid & 31;
    int m0 = blockIdx.y << 7, n0 = blockIdx.x << 7;
    int wm = warp & 1, wn = warp >> 1;   // 2 M x 2 N, warp tile 64x64

    wmma::fragment<wmma::accumulator, 16, 16, 16, float> acc[4][4];
#pragma unroll
    for (int i = 0; i < 4; i++)
#pragma unroll
        for (int j = 0; j < 4; j++) wmma::fill_fragment(acc[i][j], 0.0f);

    int KT = K / HBK;

    auto load_tile = [&](int t, int buf) {
        int k0 = t * HBK;
#pragma unroll
        for (int i = 0; i < 4; i++) {
            int idx = tid + 128 * i;
            int r = idx >> 2, c = (idx & 3) * 8;
            bool ok = (m0 + r) < M;
            cp16_sh(smem_u32(&sA[buf * HASZ + r * HLDA + c]),
                    A + (size_t)(m0 + r) * K + k0 + c, ok);
        }
#pragma unroll
        for (int i = 0; i < 4; i++) {
            int idx = tid + 128 * i;
            int r = idx >> 4, c = (idx & 15) * 8;
            cp16_sh(smem_u32(&sB[buf * HBSZ + r * HLDB + c]),
                    B + (size_t)(k0 + r) * N + n0 + c, true);
        }
        cp_commit();
    };

    // prologue: prefetch stages 0 and 1
    load_tile(0, 0);
    if (KT > 1) load_tile(1, 1);

    int cur = 0;
    for (int t = 0; t < KT; t++) {
        // issue prefetch of t+2 into the stage freed by iter t-1
        if (t + 2 < KT) load_tile(t + 2, (t + 2) % 3);
        // wait until stage t's group is complete (tail-correct step-down)
        if (t + 2 < KT)      cp_wait<2>();
        else if (t + 1 < KT) cp_wait<1>();
        else                 cp_wait<0>();
        __syncthreads();
        __half* Ab = sA + cur * HASZ;
        __half* Bb = sB + cur * HBSZ;
#pragma unroll
        for (int kk = 0; kk < HBK; kk += 16) {
            wmma::fragment<wmma::matrix_a, 16, 16, 16, __half, wmma::row_major> af[4];
            wmma::fragment<wmma::matrix_b, 16, 16, 16, __half, wmma::row_major> bf[4];
#pragma unroll
            for (int i = 0; i < 4; i++)
                wmma::load_matrix_sync(af[i], &Ab[(wm * 64 + i * 16) * HLDA + kk],
                                       HLDA);
#pragma unroll
            for (int j = 0; j < 4; j++)
                wmma::load_matrix_sync(bf[j], &Bb[kk * HLDB + wn * 64 + j * 16],
                                       HLDB);
#pragma unroll
            for (int i = 0; i < 4; i++)
#pragma unroll
                for (int j = 0; j < 4; j++)
                    wmma::mma_sync(acc[i][j], af[i], bf[j], acc[i][j]);
        }
        __syncthreads();
        cur = (cur + 1 == 3) ? 0 : cur + 1;
    }

    // epilogue: per-warp fp32 stage (16x20) in reused smem, bias+relu, half out
    float* stage = reinterpret_cast<float*>(dsm) + warp * 320;
#pragma unroll
    for (int i = 0; i < 4; i++) {
#pragma unroll
        for (int j = 0; j < 4; j++) {
            wmma::store_matrix_sync(stage, acc[i][j], 20, wmma::mem_row_major);
            __syncwarp();
            int r  = lane >> 1;
            int cs = (lane & 1) * 8;
            int gm = m0 + wm * 64 + i * 16 + r;
            int gn = n0 + wn * 64 + j * 16 + cs;
            if (gm < M) {
                const float* sp = &stage[r * 20 + cs];
                float o[8];
#pragma unroll
                for (int c = 0; c < 8; c++) {
                    float v = sp[c];
                    if (BR) v = fmaxf(v + bias[gn + c], 0.f);
                    o[c] = v;
                }
                uint4 pk;
                __half2 p0 = __floats2half2_rn(o[0], o[1]);
                __half2 p1 = __floats2half2_rn(o[2], o[3]);
                __half2 p2 = __floats2half2_rn(o[4], o[5]);
                __half2 p3 = __floats2half2_rn(o[6], o[7]);
                pk.x = *(unsigned*)&p0; pk.y = *(unsigned*)&p1;
                pk.z = *(unsigned*)&p2; pk.w = *(unsigned*)&p3;
                *(uint4*)&C[(size_t)gm * N + gn] = pk;
            }
            __syncwarp();
        }
    }
}

// ---------------- final projection 512 -> 3 (half input) ----------------
__global__ void __launch_bounds__(256) k_out3(const __half* __restrict__ h,
                                              const float* __restrict__ Wc,
                                              const float* __restrict__ bc,
                                              float* __restrict__ out) {
    __shared__ float wc[512 * 3];
    for (int i = threadIdx.x; i < 512 * 3; i += blockDim.x) wc[i] = Wc[i];
    __syncthreads();
    int gw   = (blockIdx.x * blockDim.x + threadIdx.x) >> 5;
    int lane = threadIdx.x & 31;
    if (gw >= NV) return;
    float a0 = 0.f, a1 = 0.f, a2 = 0.f;
    const __half2* hp = (const __half2*)(h + (size_t)gw * 512);
#pragma unroll
    for (int i = 0; i < 8; i++) {
        int k2 = lane + 32 * i;
        float2 hv = __half22float2(hp[k2]);
        int k = k2 * 2;
        a0 += hv.x * wc[k * 3 + 0] + hv.y * wc[(k + 1) * 3 + 0];
        a1 += hv.x * wc[k * 3 + 1] + hv.y * wc[(k + 1) * 3 + 1];
        a2 += hv.x * wc[k * 3 + 2] + hv.y * wc[(k + 1) * 3 + 2];
    }
#pragma unroll
    for (int o = 16; o; o >>= 1) {
        a0 += __shfl_xor_sync(0xFFFFFFFFu, a0, o);
        a1 += __shfl_xor_sync(0xFFFFFFFFu, a1, o);
        a2 += __shfl_xor_sync(0xFFFFFFFFu, a2, o);
    }
    if (lane == 0) {
        out[gw * 3 + 0] = a0 + bc[0];
        out[gw * 3 + 1] = a1 + bc[1];
        out[gw * 3 + 2] = a2 + bc[2];
    }
}

// ---------------- launch ----------------
extern "C" void kernel_launch(void* const* d_in, const int* in_sizes, int n_in,
                              void* d_out, int out_size) {
    const float* x  = (const float*)d_in[0];
    const void*  ei = d_in[1];
    const float* W1 = (const float*)d_in[2];
    const float* b1 = (const float*)d_in[3];
    const float* W2 = (const float*)d_in[4];
    const float* b2 = (const float*)d_in[5];
    const float* W3 = (const float*)d_in[6];
    const float* b3 = (const float*)d_in[7];
    const float* Wi = (const float*)d_in[8];
    const float* bi = (const float*)d_in[9];
    const float* Wc = (const float*)d_in[10];
    const float* bc = (const float*)d_in[11];
    float* out = (float*)d_out;

    __half *pXh, *pAh, *pHh, *pY1, *pY2, *pW1h, *pW2h, *pW3h, *pWih;
    cudaGetSymbolAddress((void**)&pXh,  g_xh);
    cudaGetSymbolAddress((void**)&pAh,  g_ah);
    cudaGetSymbolAddress((void**)&pHh,  g_hh);
    cudaGetSymbolAddress((void**)&pY1,  g_y1);
    cudaGetSymbolAddress((void**)&pY2,  g_y2);
    cudaGetSymbolAddress((void**)&pW1h, g_w1h);
    cudaGetSymbolAddress((void**)&pW2h, g_w2h);
    cudaGetSymbolAddress((void**)&pW3h, g_w3h);
    cudaGetSymbolAddress((void**)&pWih, g_wih);

    cudaFuncSetAttribute(k_hgemm<false>,
                         cudaFuncAttributeMaxDynamicSharedMemorySize, HSMEM_BYTES);
    cudaFuncSetAttribute(k_hgemm<true>,
                         cudaFuncAttributeMaxDynamicSharedMemorySize, HSMEM_BYTES);

    const int TB  = 256;
    const int NPB = (NE / 2 + TB - 1) / TB;
    const int AGB = (NV + 7) / 8;

    // idx0..2: init, W1->half, x->half
    k_init_detect<<<NBLK, TB>>>((const int*)ei);
    k_f2h<<<(128 * 128 / 4 + TB - 1) / TB, TB>>>((const float4*)W1, (uint2*)pW1h,
                                                 128 * 128 / 4);
    k_f2h<<<(NV * 128 / 4 + TB - 1) / TB, TB>>>((const float4*)x, (uint2*)pXh,
                                                NV * 128 / 4);
    // idx3: PROFILED — fp16 tensor GEMM L1 (Xh @ W1h, raw)
    k_hgemm<false><<<dim3(1, MT128), 128, HSMEM_BYTES>>>(pXh, pW1h, b1, pAh,
                                                         NV, 128, 128);

    // preprocessing + remaining weight conversions
    k_hist<<<NPB, TB>>>(ei);
    k_reduce<<<NBLK, TB>>>();
    k_scanb<<<1, 512>>>();
    k_scatter<<<NBLK, TB>>>();
    k_fill<<<NPB, TB>>>(ei);
    k_f2h<<<(128 * 128 / 4 + TB - 1) / TB, TB>>>((const float4*)W2, (uint2*)pW2h,
                                                 128 * 128 / 4);
    k_f2h<<<(128 * 512 / 4 + TB - 1) / TB, TB>>>((const float4*)W3, (uint2*)pW3h,
                                                 128 * 512 / 4);
    k_f2h<<<(512 * 512 / 4 + TB - 1) / TB, TB>>>((const float4*)Wi, (uint2*)pWih,
                                                 512 * 512 / 4);

    // L1: aggregate(XW1) + b1, relu
    k_aggh<true><<<AGB, TB>>>((const uint2*)pAh, (uint2*)pHh, (const float4*)b1);
    // L2: project then aggregate (+b2, relu)
    k_hgemm<false><<<dim3(1, MT128), 128, HSMEM_BYTES>>>(pHh, pW2h, b2, pAh,
                                                         NV, 128, 128);
    k_aggh<true><<<AGB, TB>>>((const uint2*)pAh, (uint2*)pHh, (const float4*)b2);
    // L3: aggregate (plain) then project 128->512 (+b3, relu)
    k_aggh<false><<<AGB, TB>>>((const uint2*)pHh, (uint2*)pAh, (const float4*)b3);
    k_hgemm<true><<<dim3(4, MT128), 128, HSMEM_BYTES>>>(pAh, pW3h, b3, pY1,
                                                        NV, 128, 512);
    // MLP 512->512 (+bi, relu)
    k_hgemm<true><<<dim3(4, MT128), 128, HSMEM_BYTES>>>(pY1, pWih, bi, pY2,
                                                        NV, 512, 512);
    // classifier
    k_out3<<<(NV * 32 + TB - 1) / TB, TB>>>(pY2, Wc, bc, out);
}